// round 1
// baseline (speedup 1.0000x reference)
#include <cuda_runtime.h>
#include <math.h>

#define BB    8
#define NN    4096
#define CC    512
#define NTOK  (BB*NN)        // 32768 tokens
#define HEADS 8
#define HD    64
#define HH    64
#define WW    64
#define EPSF  1e-5f
#define CLAMPF 100.0f

// ---------------- scratch (static device globals; no runtime alloc) ----------
__device__ float g_normed[NTOK*CC];          // 64 MB
__device__ float g_qkv[(size_t)NTOK*3*CC];   // 192 MB
__device__ float g_attn[NTOK*CC];            // 64 MB (pre-projection attention out)
__device__ float g_attnproj[NTOK*CC];        // 64 MB
__device__ float g_t[NTOK*CC];               // 64 MB (lcm layernorm out, token-major)
__device__ float g_y[NTOK*CC];               // 64 MB (conv1+gelu out, token-major [b,n,c])
__device__ float g_kv[BB*HEADS*HD*HD];       // 1 MB
__device__ float g_ksum[BB*HEADS*HD];
__device__ float g_sum[CC];
__device__ float g_sumsq[CC];

// ---------------- layernorm over C=512, one block (128 thr) per token --------
__global__ void ln_kernel(const float* __restrict__ in,
                          const float* __restrict__ gamma,
                          const float* __restrict__ beta,
                          float* __restrict__ out)
{
    int token = blockIdx.x;
    const float4* row = (const float4*)(in + (size_t)token * CC);
    float4* orow = (float4*)(out + (size_t)token * CC);
    int tid = threadIdx.x;                    // 0..127
    float4 v = row[tid];
    float s  = v.x + v.y + v.z + v.w;
    float sq = v.x*v.x + v.y*v.y + v.z*v.z + v.w*v.w;
    #pragma unroll
    for (int o = 16; o; o >>= 1) {
        s  += __shfl_xor_sync(0xffffffffu, s,  o);
        sq += __shfl_xor_sync(0xffffffffu, sq, o);
    }
    __shared__ float ss[4], ssq[4];
    if ((tid & 31) == 0) { ss[tid >> 5] = s; ssq[tid >> 5] = sq; }
    __syncthreads();
    float ts = ss[0] + ss[1] + ss[2] + ss[3];
    float tq = ssq[0] + ssq[1] + ssq[2] + ssq[3];
    float mean = ts * (1.0f / CC);
    float var  = tq * (1.0f / CC) - mean * mean;
    float inv  = rsqrtf(var + EPSF);
    float4 g4 = ((const float4*)gamma)[tid];
    float4 b4 = ((const float4*)beta)[tid];
    float4 o;
    o.x = (v.x - mean) * inv * g4.x + b4.x;
    o.y = (v.y - mean) * inv * g4.y + b4.y;
    o.z = (v.z - mean) * inv * g4.z + b4.z;
    o.w = (v.w - mean) * inv * g4.w + b4.w;
    orow[tid] = o;
}

// ---------------- SGEMM: C[M,N] = A[M,K] @ B[K,N] + bias, relu on cols<NRELU -
// BM=128 BN=128 BK=8, 256 threads, 8x8 per thread.
template<int NRELU>
__global__ __launch_bounds__(256)
void sgemm_kernel(const float* __restrict__ A, const float* __restrict__ B,
                  const float* __restrict__ bias, float* __restrict__ Cm,
                  int M, int Nn, int Kk)
{
    __shared__ float As[8][128];
    __shared__ float Bs[8][128];
    int tid = threadIdx.x;
    int row0 = blockIdx.y * 128;
    int col0 = blockIdx.x * 128;
    int arow = tid >> 1;            // 0..127
    int acol = (tid & 1) * 4;       // 0,4
    int brow = tid >> 5;            // 0..7
    int bcol = (tid & 31) * 4;      // 0..124
    int ty = tid >> 4, tx = tid & 15;
    float acc[8][8];
    #pragma unroll
    for (int i = 0; i < 8; i++)
        #pragma unroll
        for (int j = 0; j < 8; j++) acc[i][j] = 0.f;
    const float* Aptr = A + (size_t)(row0 + arow) * Kk + acol;
    const float* Bptr = B + (size_t)brow * Nn + col0 + bcol;
    for (int k0 = 0; k0 < Kk; k0 += 8) {
        float4 a = *(const float4*)(Aptr + k0);
        As[acol + 0][arow] = a.x;
        As[acol + 1][arow] = a.y;
        As[acol + 2][arow] = a.z;
        As[acol + 3][arow] = a.w;
        float4 b = *(const float4*)(Bptr + (size_t)k0 * Nn);
        *(float4*)&Bs[brow][bcol] = b;
        __syncthreads();
        #pragma unroll
        for (int k = 0; k < 8; k++) {
            float ra[8], rb[8];
            *(float4*)&ra[0] = *(const float4*)&As[k][ty * 8];
            *(float4*)&ra[4] = *(const float4*)&As[k][ty * 8 + 4];
            *(float4*)&rb[0] = *(const float4*)&Bs[k][tx * 8];
            *(float4*)&rb[4] = *(const float4*)&Bs[k][tx * 8 + 4];
            #pragma unroll
            for (int i = 0; i < 8; i++)
                #pragma unroll
                for (int j = 0; j < 8; j++)
                    acc[i][j] += ra[i] * rb[j];
        }
        __syncthreads();
    }
    #pragma unroll
    for (int i = 0; i < 8; i++) {
        int r = row0 + ty * 8 + i;
        #pragma unroll
        for (int j = 0; j < 8; j += 4) {
            int c = col0 + tx * 8 + j;
            float4 o;
            o.x = acc[i][j + 0] + bias[c + 0];
            o.y = acc[i][j + 1] + bias[c + 1];
            o.z = acc[i][j + 2] + bias[c + 2];
            o.w = acc[i][j + 3] + bias[c + 3];
            if (c < NRELU) {
                o.x = fmaxf(o.x, 0.f); o.y = fmaxf(o.y, 0.f);
                o.z = fmaxf(o.z, 0.f); o.w = fmaxf(o.w, 0.f);
            }
            *(float4*)(Cm + (size_t)r * Nn + c) = o;
        }
    }
}

// ---------------- zero scratch accumulators ---------------------------------
__global__ void zero_kernel()
{
    int i = blockIdx.x * blockDim.x + threadIdx.x;
    if (i < BB*HEADS*HD*HD) g_kv[i] = 0.f;
    if (i < BB*HEADS*HD)    g_ksum[i] = 0.f;
    if (i < CC)           { g_sum[i] = 0.f; g_sumsq[i] = 0.f; }
}

// ---------------- kv = k^T v per (b,h); ksum = sum_n k --------------------
// grid (64 bh, 16 chunks of 256 rows), 256 threads; 4x4 out tile per thread.
__global__ __launch_bounds__(256)
void kv_kernel(const float* __restrict__ qkv)
{
    int bh = blockIdx.x;
    int b = bh >> 3, h = bh & 7;
    const float* kbase = qkv + (size_t)(b*NN)*1536 +  512 + h*64;
    const float* vbase = qkv + (size_t)(b*NN)*1536 + 1024 + h*64;
    __shared__ float ks[64][64];
    __shared__ float vs[64][64];
    int tid = threadIdx.x;
    int lr = tid >> 4;           // 0..15 (row within load pass)
    int lc = (tid & 15) * 4;     // 0..60 (col)
    int ty = tid >> 4, tx = tid & 15;
    float acc[4][4];
    #pragma unroll
    for (int i = 0; i < 4; i++)
        #pragma unroll
        for (int j = 0; j < 4; j++) acc[i][j] = 0.f;
    float ksum4[4] = {0.f, 0.f, 0.f, 0.f};
    int n0 = blockIdx.y * 256;
    for (int s = 0; s < 4; s++) {
        int base = n0 + s * 64;
        #pragma unroll
        for (int p = 0; p < 4; p++) {
            int r = p * 16 + lr;
            float4 kk = *(const float4*)(kbase + (size_t)(base + r) * 1536 + lc);
            float4 vv = *(const float4*)(vbase + (size_t)(base + r) * 1536 + lc);
            *(float4*)&ks[r][lc] = kk;
            *(float4*)&vs[r][lc] = vv;
            ksum4[0] += kk.x; ksum4[1] += kk.y; ksum4[2] += kk.z; ksum4[3] += kk.w;
        }
        __syncthreads();
        #pragma unroll 8
        for (int n = 0; n < 64; n++) {
            float rk[4], rv[4];
            *(float4*)rk = *(const float4*)&ks[n][ty * 4];
            *(float4*)rv = *(const float4*)&vs[n][tx * 4];
            #pragma unroll
            for (int i = 0; i < 4; i++)
                #pragma unroll
                for (int j = 0; j < 4; j++)
                    acc[i][j] += rk[i] * rv[j];
        }
        __syncthreads();
    }
    float* kvout = g_kv + bh * 4096;
    #pragma unroll
    for (int i = 0; i < 4; i++)
        #pragma unroll
        for (int j = 0; j < 4; j++)
            atomicAdd(&kvout[(ty*4 + i) * 64 + tx*4 + j], acc[i][j]);
    #pragma unroll
    for (int i = 0; i < 4; i++)
        atomicAdd(&g_ksum[bh * 64 + lc + i], ksum4[i]);
}

// ---------------- attn = (q @ kv) / max(q . norm, 100) -----------------------
// grid (64 bh, 128 chunks of 32 tokens), 256 threads = 4 tokens x 64 lanes.
__global__ __launch_bounds__(256)
void attn_kernel(const float* __restrict__ qkv, float* __restrict__ attn)
{
    int bh = blockIdx.x;
    int b = bh >> 3, h = bh & 7;
    __shared__ float kvs[64][64];
    __shared__ float norms[64];
    __shared__ float qs[4][64];
    int tid = threadIdx.x;
    for (int i = tid; i < 4096; i += 256)
        kvs[i >> 6][i & 63] = g_kv[bh * 4096 + i];
    if (tid < 64) norms[tid] = fmaxf(g_ksum[bh * 64 + tid], CLAMPF);
    __syncthreads();
    int tg = tid >> 6;     // token subgroup 0..3
    int e  = tid & 63;
    const float* qbase = qkv + (size_t)(b*NN)*1536 + h*64;
    for (int it = 0; it < 8; it++) {
        int n = blockIdx.y * 32 + it * 4 + tg;
        qs[tg][e] = qbase[(size_t)n * 1536 + e];
        __syncthreads();
        float acc = 0.f, den = 0.f;
        #pragma unroll
        for (int d = 0; d < 64; d++) {
            float qd = qs[tg][d];
            acc += qd * kvs[d][e];
            den += qd * norms[d];
        }
        den = fmaxf(den, CLAMPF);
        attn[(size_t)(b*NN + n) * CC + h*64 + e] = acc / den;
        __syncthreads();
    }
}

// ---------------- conv1: depthwise 7x7 + bias + gelu + channel stats ---------
// grid (64 spatial tiles 8x8, 16 ctiles, 8 b), 256 threads. Tile 8h x 8w x 32c.
__global__ __launch_bounds__(256)
void conv1_kernel(const float* __restrict__ t, const float* __restrict__ cw,
                  const float* __restrict__ cb)
{
    int b  = blockIdx.z;
    int c0 = blockIdx.y * 32;
    int h0 = (blockIdx.x >> 3) * 8;
    int w0 = (blockIdx.x & 7) * 8;
    __shared__ float ins[14][14][32];
    __shared__ float ws[32][49];
    __shared__ float rsum[8][32], rsq[8][32];
    int tid = threadIdx.x;
    for (int i = tid; i < 32 * 49; i += 256)
        ws[i / 49][i % 49] = cw[(c0 + i / 49) * 49 + (i % 49)];
    for (int i = tid; i < 14 * 14 * 32; i += 256) {
        int ic = i & 31; int pos = i >> 5;
        int iw = pos % 14, ih = pos / 14;
        int gh = h0 + ih - 3, gw = w0 + iw - 3;
        float v = 0.f;
        if (gh >= 0 && gh < HH && gw >= 0 && gw < WW)
            v = t[((size_t)(b*NN) + gh*WW + gw) * CC + c0 + ic];
        ins[ih][iw][ic] = v;
    }
    __syncthreads();
    int oc = tid & 31;
    int ow = tid >> 5;
    float bias = cb[c0 + oc];
    float psum = 0.f, psq = 0.f;
    for (int oh = 0; oh < 8; oh++) {
        float acc = bias;
        #pragma unroll
        for (int dh = 0; dh < 7; dh++)
            #pragma unroll
            for (int dw = 0; dw < 7; dw++)
                acc += ins[oh + dh][ow + dw][oc] * ws[oc][dh * 7 + dw];
        float yv = acc * normcdff(acc);           // exact gelu
        g_y[((size_t)(b*NN) + (h0+oh)*WW + (w0+ow)) * CC + c0 + oc] = yv;
        psum += yv; psq += yv * yv;
    }
    rsum[ow][oc] = psum; rsq[ow][oc] = psq;
    __syncthreads();
    if (tid < 32) {
        float s = 0.f, q = 0.f;
        #pragma unroll
        for (int i = 0; i < 8; i++) { s += rsum[i][tid]; q += rsq[i][tid]; }
        atomicAdd(&g_sum[c0 + tid], s);
        atomicAdd(&g_sumsq[c0 + tid], q);
    }
}

// ---------------- conv2: BN-apply + depthwise 7x7 + triple residual ----------
__global__ __launch_bounds__(256)
void conv2_kernel(const float* __restrict__ x, const float* __restrict__ cw,
                  const float* __restrict__ cb, const float* __restrict__ bng,
                  const float* __restrict__ bnb, float* __restrict__ out)
{
    int b  = blockIdx.z;
    int c0 = blockIdx.y * 32;
    int h0 = (blockIdx.x >> 3) * 8;
    int w0 = (blockIdx.x & 7) * 8;
    __shared__ float ins[14][14][32];
    __shared__ float ws[32][49];
    __shared__ float scs[32], shs[32];
    int tid = threadIdx.x;
    if (tid < 32) {
        int c = c0 + tid;
        float m   = g_sum[c]   * (1.0f / (float)NTOK);
        float var = g_sumsq[c] * (1.0f / (float)NTOK) - m * m;
        float inv = rsqrtf(var + EPSF);
        float sc = bng[c] * inv;
        scs[tid] = sc;
        shs[tid] = bnb[c] - m * sc;
    }
    __syncthreads();
    for (int i = tid; i < 32 * 49; i += 256)
        ws[i / 49][i % 49] = cw[(c0 + i / 49) * 49 + (i % 49)];
    for (int i = tid; i < 14 * 14 * 32; i += 256) {
        int ic = i & 31; int pos = i >> 5;
        int iw = pos % 14, ih = pos / 14;
        int gh = h0 + ih - 3, gw = w0 + iw - 3;
        float v = 0.f;
        if (gh >= 0 && gh < HH && gw >= 0 && gw < WW)
            v = g_y[((size_t)(b*NN) + gh*WW + gw) * CC + c0 + ic] * scs[ic] + shs[ic];
        ins[ih][iw][ic] = v;
    }
    __syncthreads();
    int oc = tid & 31;
    int ow = tid >> 5;
    float bias = cb[c0 + oc];
    for (int oh = 0; oh < 8; oh++) {
        float acc = bias;
        #pragma unroll
        for (int dh = 0; dh < 7; dh++)
            #pragma unroll
            for (int dw = 0; dw < 7; dw++)
                acc += ins[oh + dh][ow + dw][oc] * ws[oc][dh * 7 + dw];
        size_t idx = ((size_t)(b*NN) + (h0+oh)*WW + (w0+ow)) * CC + c0 + oc;
        out[idx] = x[idx] + g_attnproj[idx] + acc;
    }
}

// ---------------- launch ----------------------------------------------------
extern "C" void kernel_launch(void* const* d_in, const int* in_sizes, int n_in,
                              void* d_out, int out_size)
{
    const float* x      = (const float*)d_in[0];
    const float* qkv_w  = (const float*)d_in[1];
    const float* qkv_b  = (const float*)d_in[2];
    const float* out_w  = (const float*)d_in[3];
    const float* out_b  = (const float*)d_in[4];
    const float* pre_g  = (const float*)d_in[5];
    const float* pre_b  = (const float*)d_in[6];
    const float* lcm_g  = (const float*)d_in[7];
    const float* lcm_b  = (const float*)d_in[8];
    const float* ci_w   = (const float*)d_in[9];
    const float* ci_b   = (const float*)d_in[10];
    const float* bn_g   = (const float*)d_in[11];
    const float* bn_b   = (const float*)d_in[12];
    const float* co_w   = (const float*)d_in[13];
    const float* co_b   = (const float*)d_in[14];
    float* out = (float*)d_out;

    float *p_normed, *p_qkv, *p_attn, *p_attnproj, *p_t;
    cudaGetSymbolAddress((void**)&p_normed,   g_normed);
    cudaGetSymbolAddress((void**)&p_qkv,      g_qkv);
    cudaGetSymbolAddress((void**)&p_attn,     g_attn);
    cudaGetSymbolAddress((void**)&p_attnproj, g_attnproj);
    cudaGetSymbolAddress((void**)&p_t,        g_t);

    // 1. pre-layernorm
    ln_kernel<<<NTOK, 128>>>(x, pre_g, pre_b, p_normed);
    // zero accumulators (kv, ksum, bn stats)
    zero_kernel<<<(BB*HEADS*HD*HD + 255) / 256, 256>>>();
    // 2. qkv gemm (+relu on q,k columns [0,1024))
    sgemm_kernel<1024><<<dim3(1536/128, NTOK/128), 256>>>(
        p_normed, qkv_w, qkv_b, p_qkv, NTOK, 1536, CC);
    // 3. kv outer-product + ksum
    kv_kernel<<<dim3(BB*HEADS, 16), 256>>>(p_qkv);
    // 4. attention apply
    attn_kernel<<<dim3(BB*HEADS, 128), 256>>>(p_qkv, p_attn);
    // 5. output projection
    sgemm_kernel<0><<<dim3(CC/128, NTOK/128), 256>>>(
        p_attn, out_w, out_b, p_attnproj, NTOK, CC, CC);
    // 6. lcm layernorm
    ln_kernel<<<NTOK, 128>>>(p_attnproj, lcm_g, lcm_b, p_t);
    // 7. conv1 + gelu + bn stats
    conv1_kernel<<<dim3(64, CC/32, BB), 256>>>(p_t, ci_w, ci_b);
    // 8. bn apply + conv2 + residual sum -> out
    conv2_kernel<<<dim3(64, CC/32, BB), 256>>>(x, co_w, co_b, bn_g, bn_b, out);
}

// round 3
// speedup vs baseline: 1.7865x; 1.7865x over previous
#include <cuda_runtime.h>
#include <math.h>
#include <cstdint>

#define BB    8
#define NN    4096
#define CC    512
#define NTOK  (BB*NN)        // 32768 tokens
#define HEADS 8
#define HD    64
#define HH    64
#define WW    64
#define EPSF  1e-5f
#define CLAMPF 100.0f

// ---------------- scratch (static device globals; no runtime alloc) ----------
__device__ float g_normed[NTOK*CC];          // 64 MB
__device__ float g_qkv[(size_t)NTOK*3*CC];   // 192 MB
__device__ float g_attn[NTOK*CC];            // 64 MB
__device__ float g_attnproj[NTOK*CC];        // 64 MB
__device__ float g_t[NTOK*CC];               // 64 MB
__device__ float g_y[NTOK*CC];               // 64 MB
__device__ float g_kv[BB*HEADS*HD*HD];
__device__ float g_ksum[BB*HEADS*HD];
__device__ float g_sum[CC];
__device__ float g_sumsq[CC];
__device__ float g_wqkvT[3*CC*CC];           // [1536,512] transposed qkv weights
__device__ float g_woutT[CC*CC];             // [512,512]  transposed out weights

// ============================ PTX helpers ====================================
__device__ __forceinline__ uint32_t smem_u32(const void* p){
    uint32_t a;
    asm("{ .reg .u64 t; cvta.to.shared.u64 t, %1; cvt.u32.u64 %0, t; }"
        : "=r"(a) : "l"(p));
    return a;
}
__device__ __forceinline__ void cpa16(uint32_t dst, const void* src){
    asm volatile("cp.async.ca.shared.global [%0], [%1], 16;"
                 :: "r"(dst), "l"(src) : "memory");
}
__device__ __forceinline__ void cpa_commit(){
    asm volatile("cp.async.commit_group;" ::: "memory");
}
template<int N> __device__ __forceinline__ void cpa_wait(){
    asm volatile("cp.async.wait_group %0;" :: "n"(N) : "memory");
}
__device__ __forceinline__ void mma_tf32(float* d, const uint32_t* a, const uint32_t* b){
    asm volatile("mma.sync.aligned.m16n8k8.row.col.f32.tf32.tf32.f32 "
        "{%0,%1,%2,%3}, {%4,%5,%6,%7}, {%8,%9}, {%0,%1,%2,%3};"
        : "+f"(d[0]), "+f"(d[1]), "+f"(d[2]), "+f"(d[3])
        : "r"(a[0]), "r"(a[1]), "r"(a[2]), "r"(a[3]), "r"(b[0]), "r"(b[1]));
}

// ============================ mma.sync tf32 GEMM =============================
// D[M,Nn] = A[M,512] @ Bt[Nn,512]^T + bias, relu on cols < nrelu.
// CTA tile 128x128, 8 warps (4m x 2n), warp tile 32x64. BK=16, double buffer.
#define GK   512
#define GBK  16
#define KPAD 20
#define NKT  (GK/GBK)   // 32 k-tiles

__global__ void __launch_bounds__(256)
gemm_mma_kernel(const float* __restrict__ A, const float* __restrict__ Bt,
                const float* __restrict__ bias, float* __restrict__ Cout,
                int Nn, int nrelu)
{
    __shared__ float As[2][128][KPAD];
    __shared__ float Bs[2][128][KPAD];
    int tid = threadIdx.x;
    int wid = tid >> 5, lane = tid & 31;
    int gid = lane >> 2, tig = lane & 3;
    int warpM = (wid >> 1) * 32;
    int warpN = (wid & 1) * 64;
    int row0 = blockIdx.y * 128, col0 = blockIdx.x * 128;
    const float* Ab = A  + (size_t)row0 * GK;
    const float* Bb = Bt + (size_t)col0 * GK;

    // per-thread cp.async assignments: 4 chunks (2 A + 2 B)
    int lr0 = tid >> 2,          lc0 = (tid & 3) * 4;         // chunk tid
    int lr1 = (tid + 256) >> 2,  lc1 = lc0;                   // chunk tid+256
    uint32_t sA0 = smem_u32(&As[0][lr0][lc0]);
    uint32_t sA1 = smem_u32(&As[0][lr1][lc1]);
    uint32_t sB0 = smem_u32(&Bs[0][lr0][lc0]);
    uint32_t sB1 = smem_u32(&Bs[0][lr1][lc1]);
    const uint32_t stageOff = 128 * KPAD * 4;

    float acc[2][8][4];
    #pragma unroll
    for (int mi = 0; mi < 2; mi++)
        #pragma unroll
        for (int ni = 0; ni < 8; ni++)
            #pragma unroll
            for (int r = 0; r < 4; r++) acc[mi][ni][r] = 0.f;

    auto load_tile = [&](int t, int b){
        int k0 = t * GBK;
        uint32_t so = b * stageOff;
        cpa16(sA0 + so, Ab + (size_t)lr0 * GK + k0 + lc0);
        cpa16(sA1 + so, Ab + (size_t)lr1 * GK + k0 + lc1);
        cpa16(sB0 + so, Bb + (size_t)lr0 * GK + k0 + lc0);
        cpa16(sB1 + so, Bb + (size_t)lr1 * GK + k0 + lc1);
    };

    load_tile(0, 0);
    cpa_commit();

    for (int t = 0; t < NKT; t++){
        int cb = t & 1;
        if (t + 1 < NKT) load_tile(t + 1, (t + 1) & 1);
        cpa_commit();
        cpa_wait<1>();
        __syncthreads();
        #pragma unroll
        for (int ks = 0; ks < 2; ks++){
            int k0 = ks * 8;
            uint32_t a[2][4], b[8][2];
            #pragma unroll
            for (int mi = 0; mi < 2; mi++){
                int m = warpM + mi * 16 + gid;
                a[mi][0] = __float_as_uint(As[cb][m    ][k0 + tig]);
                a[mi][1] = __float_as_uint(As[cb][m + 8][k0 + tig]);
                a[mi][2] = __float_as_uint(As[cb][m    ][k0 + tig + 4]);
                a[mi][3] = __float_as_uint(As[cb][m + 8][k0 + tig + 4]);
            }
            #pragma unroll
            for (int ni = 0; ni < 8; ni++){
                int n = warpN + ni * 8 + gid;
                b[ni][0] = __float_as_uint(Bs[cb][n][k0 + tig]);
                b[ni][1] = __float_as_uint(Bs[cb][n][k0 + tig + 4]);
            }
            #pragma unroll
            for (int mi = 0; mi < 2; mi++)
                #pragma unroll
                for (int ni = 0; ni < 8; ni++)
                    mma_tf32(acc[mi][ni], a[mi], b[ni]);
        }
        __syncthreads();
    }

    // epilogue: bias + optional relu, direct global stores (float2 per frag row)
    #pragma unroll
    for (int mi = 0; mi < 2; mi++){
        #pragma unroll
        for (int rr = 0; rr < 2; rr++){
            int r = row0 + warpM + mi * 16 + rr * 8 + gid;
            #pragma unroll
            for (int ni = 0; ni < 8; ni++){
                int c = col0 + warpN + ni * 8 + tig * 2;
                float2 o;
                o.x = acc[mi][ni][rr * 2 + 0] + bias[c + 0];
                o.y = acc[mi][ni][rr * 2 + 1] + bias[c + 1];
                if (c < nrelu){
                    o.x = fmaxf(o.x, 0.f);
                    o.y = fmaxf(o.y, 0.f);
                }
                *(float2*)(Cout + (size_t)r * Nn + c) = o;
            }
        }
    }
}

// ---------------- weight transpose: out[n][k] = in[k][n] ---------------------
__global__ void transpose_kernel(const float* __restrict__ in,
                                 float* __restrict__ outp, int R, int Cc)
{
    __shared__ float tile[32][33];
    int bx = blockIdx.x * 32, by = blockIdx.y * 32;
    int tx = threadIdx.x, ty = threadIdx.y;   // 32 x 8
    #pragma unroll
    for (int i = 0; i < 32; i += 8)
        tile[ty + i][tx] = in[(size_t)(by + ty + i) * Cc + bx + tx];
    __syncthreads();
    #pragma unroll
    for (int i = 0; i < 32; i += 8)
        outp[(size_t)(bx + ty + i) * R + by + tx] = tile[tx][ty + i];
}

// ---------------- layernorm over C=512, one block (128 thr) per token --------
__global__ void ln_kernel(const float* __restrict__ in,
                          const float* __restrict__ gamma,
                          const float* __restrict__ beta,
                          float* __restrict__ out)
{
    int token = blockIdx.x;
    const float4* row = (const float4*)(in + (size_t)token * CC);
    float4* orow = (float4*)(out + (size_t)token * CC);
    int tid = threadIdx.x;
    float4 v = row[tid];
    float s  = v.x + v.y + v.z + v.w;
    float sq = v.x*v.x + v.y*v.y + v.z*v.z + v.w*v.w;
    #pragma unroll
    for (int o = 16; o; o >>= 1) {
        s  += __shfl_xor_sync(0xffffffffu, s,  o);
        sq += __shfl_xor_sync(0xffffffffu, sq, o);
    }
    __shared__ float ss[4], ssq[4];
    if ((tid & 31) == 0) { ss[tid >> 5] = s; ssq[tid >> 5] = sq; }
    __syncthreads();
    float ts = ss[0] + ss[1] + ss[2] + ss[3];
    float tq = ssq[0] + ssq[1] + ssq[2] + ssq[3];
    float mean = ts * (1.0f / CC);
    float var  = tq * (1.0f / CC) - mean * mean;
    float inv  = rsqrtf(var + EPSF);
    float4 g4 = ((const float4*)gamma)[tid];
    float4 b4 = ((const float4*)beta)[tid];
    float4 o;
    o.x = (v.x - mean) * inv * g4.x + b4.x;
    o.y = (v.y - mean) * inv * g4.y + b4.y;
    o.z = (v.z - mean) * inv * g4.z + b4.z;
    o.w = (v.w - mean) * inv * g4.w + b4.w;
    orow[tid] = o;
}

// ---------------- zero scratch accumulators ---------------------------------
__global__ void zero_kernel()
{
    int i = blockIdx.x * blockDim.x + threadIdx.x;
    if (i < BB*HEADS*HD*HD) g_kv[i] = 0.f;
    if (i < BB*HEADS*HD)    g_ksum[i] = 0.f;
    if (i < CC)           { g_sum[i] = 0.f; g_sumsq[i] = 0.f; }
}

// ---------------- kv = k^T v per (b,h); ksum = sum_n k -----------------------
__global__ __launch_bounds__(256)
void kv_kernel(const float* __restrict__ qkv)
{
    int bh = blockIdx.x;
    int b = bh >> 3, h = bh & 7;
    const float* kbase = qkv + (size_t)(b*NN)*1536 +  512 + h*64;
    const float* vbase = qkv + (size_t)(b*NN)*1536 + 1024 + h*64;
    __shared__ float ks[64][64];
    __shared__ float vs[64][64];
    int tid = threadIdx.x;
    int lr = tid >> 4;
    int lc = (tid & 15) * 4;
    int ty = tid >> 4, tx = tid & 15;
    float acc[4][4];
    #pragma unroll
    for (int i = 0; i < 4; i++)
        #pragma unroll
        for (int j = 0; j < 4; j++) acc[i][j] = 0.f;
    float ksum4[4] = {0.f, 0.f, 0.f, 0.f};
    int n0 = blockIdx.y * 256;
    for (int s = 0; s < 4; s++) {
        int base = n0 + s * 64;
        #pragma unroll
        for (int p = 0; p < 4; p++) {
            int r = p * 16 + lr;
            float4 kk = *(const float4*)(kbase + (size_t)(base + r) * 1536 + lc);
            float4 vv = *(const float4*)(vbase + (size_t)(base + r) * 1536 + lc);
            *(float4*)&ks[r][lc] = kk;
            *(float4*)&vs[r][lc] = vv;
            ksum4[0] += kk.x; ksum4[1] += kk.y; ksum4[2] += kk.z; ksum4[3] += kk.w;
        }
        __syncthreads();
        #pragma unroll 8
        for (int n = 0; n < 64; n++) {
            float rk[4], rv[4];
            *(float4*)rk = *(const float4*)&ks[n][ty * 4];
            *(float4*)rv = *(const float4*)&vs[n][tx * 4];
            #pragma unroll
            for (int i = 0; i < 4; i++)
                #pragma unroll
                for (int j = 0; j < 4; j++)
                    acc[i][j] += rk[i] * rv[j];
        }
        __syncthreads();
    }
    float* kvout = g_kv + bh * 4096;
    #pragma unroll
    for (int i = 0; i < 4; i++)
        #pragma unroll
        for (int j = 0; j < 4; j++)
            atomicAdd(&kvout[(ty*4 + i) * 64 + tx*4 + j], acc[i][j]);
    #pragma unroll
    for (int i = 0; i < 4; i++)
        atomicAdd(&g_ksum[bh * 64 + lc + i], ksum4[i]);
}

// ---------------- attn = (q @ kv) / max(q . norm, 100) -----------------------
__global__ __launch_bounds__(256)
void attn_kernel(const float* __restrict__ qkv, float* __restrict__ attn)
{
    int bh = blockIdx.x;
    int b = bh >> 3, h = bh & 7;
    __shared__ float kvs[64][64];
    __shared__ float norms[64];
    __shared__ float qs[4][64];
    int tid = threadIdx.x;
    for (int i = tid; i < 4096; i += 256)
        kvs[i >> 6][i & 63] = g_kv[bh * 4096 + i];
    if (tid < 64) norms[tid] = fmaxf(g_ksum[bh * 64 + tid], CLAMPF);
    __syncthreads();
    int tg = tid >> 6;
    int e  = tid & 63;
    const float* qbase = qkv + (size_t)(b*NN)*1536 + h*64;
    for (int it = 0; it < 8; it++) {
        int n = blockIdx.y * 32 + it * 4 + tg;
        qs[tg][e] = qbase[(size_t)n * 1536 + e];
        __syncthreads();
        float acc = 0.f, den = 0.f;
        #pragma unroll
        for (int d = 0; d < 64; d++) {
            float qd = qs[tg][d];
            acc += qd * kvs[d][e];
            den += qd * norms[d];
        }
        den = fmaxf(den, CLAMPF);
        attn[(size_t)(b*NN + n) * CC + h*64 + e] = acc / den;
        __syncthreads();
    }
}

// ---------------- conv1: depthwise 7x7 + bias + gelu + channel stats ---------
__global__ __launch_bounds__(256)
void conv1_kernel(const float* __restrict__ t, const float* __restrict__ cw,
                  const float* __restrict__ cb)
{
    int b  = blockIdx.z;
    int c0 = blockIdx.y * 32;
    int h0 = (blockIdx.x >> 3) * 8;
    int w0 = (blockIdx.x & 7) * 8;
    __shared__ float ins[14][14][32];
    __shared__ float ws[32][49];
    __shared__ float rsum[8][32], rsq[8][32];
    int tid = threadIdx.x;
    for (int i = tid; i < 32 * 49; i += 256)
        ws[i / 49][i % 49] = cw[(c0 + i / 49) * 49 + (i % 49)];
    for (int i = tid; i < 14 * 14 * 32; i += 256) {
        int ic = i & 31; int pos = i >> 5;
        int iw = pos % 14, ih = pos / 14;
        int gh = h0 + ih - 3, gw = w0 + iw - 3;
        float v = 0.f;
        if (gh >= 0 && gh < HH && gw >= 0 && gw < WW)
            v = t[((size_t)(b*NN) + gh*WW + gw) * CC + c0 + ic];
        ins[ih][iw][ic] = v;
    }
    __syncthreads();
    int oc = tid & 31;
    int ow = tid >> 5;
    float bias = cb[c0 + oc];
    float psum = 0.f, psq = 0.f;
    for (int oh = 0; oh < 8; oh++) {
        float acc = bias;
        #pragma unroll
        for (int dh = 0; dh < 7; dh++)
            #pragma unroll
            for (int dw = 0; dw < 7; dw++)
                acc += ins[oh + dh][ow + dw][oc] * ws[oc][dh * 7 + dw];
        float yv = acc * normcdff(acc);
        g_y[((size_t)(b*NN) + (h0+oh)*WW + (w0+ow)) * CC + c0 + oc] = yv;
        psum += yv; psq += yv * yv;
    }
    rsum[ow][oc] = psum; rsq[ow][oc] = psq;
    __syncthreads();
    if (tid < 32) {
        float s = 0.f, q = 0.f;
        #pragma unroll
        for (int i = 0; i < 8; i++) { s += rsum[i][tid]; q += rsq[i][tid]; }
        atomicAdd(&g_sum[c0 + tid], s);
        atomicAdd(&g_sumsq[c0 + tid], q);
    }
}

// ---------------- conv2: BN-apply + depthwise 7x7 + triple residual ----------
__global__ __launch_bounds__(256)
void conv2_kernel(const float* __restrict__ x, const float* __restrict__ cw,
                  const float* __restrict__ cb, const float* __restrict__ bng,
                  const float* __restrict__ bnb, float* __restrict__ out)
{
    int b  = blockIdx.z;
    int c0 = blockIdx.y * 32;
    int h0 = (blockIdx.x >> 3) * 8;
    int w0 = (blockIdx.x & 7) * 8;
    __shared__ float ins[14][14][32];
    __shared__ float ws[32][49];
    __shared__ float scs[32], shs[32];
    int tid = threadIdx.x;
    if (tid < 32) {
        int c = c0 + tid;
        float m   = g_sum[c]   * (1.0f / (float)NTOK);
        float var = g_sumsq[c] * (1.0f / (float)NTOK) - m * m;
        float inv = rsqrtf(var + EPSF);
        float sc = bng[c] * inv;
        scs[tid] = sc;
        shs[tid] = bnb[c] - m * sc;
    }
    __syncthreads();
    for (int i = tid; i < 32 * 49; i += 256)
        ws[i / 49][i % 49] = cw[(c0 + i / 49) * 49 + (i % 49)];
    for (int i = tid; i < 14 * 14 * 32; i += 256) {
        int ic = i & 31; int pos = i >> 5;
        int iw = pos % 14, ih = pos / 14;
        int gh = h0 + ih - 3, gw = w0 + iw - 3;
        float v = 0.f;
        if (gh >= 0 && gh < HH && gw >= 0 && gw < WW)
            v = g_y[((size_t)(b*NN) + gh*WW + gw) * CC + c0 + ic] * scs[ic] + shs[ic];
        ins[ih][iw][ic] = v;
    }
    __syncthreads();
    int oc = tid & 31;
    int ow = tid >> 5;
    float bias = cb[c0 + oc];
    for (int oh = 0; oh < 8; oh++) {
        float acc = bias;
        #pragma unroll
        for (int dh = 0; dh < 7; dh++)
            #pragma unroll
            for (int dw = 0; dw < 7; dw++)
                acc += ins[oh + dh][ow + dw][oc] * ws[oc][dh * 7 + dw];
        size_t idx = ((size_t)(b*NN) + (h0+oh)*WW + (w0+ow)) * CC + c0 + oc;
        out[idx] = x[idx] + g_attnproj[idx] + acc;
    }
}

// ---------------- launch ----------------------------------------------------
extern "C" void kernel_launch(void* const* d_in, const int* in_sizes, int n_in,
                              void* d_out, int out_size)
{
    const float* x      = (const float*)d_in[0];
    const float* qkv_w  = (const float*)d_in[1];
    const float* qkv_b  = (const float*)d_in[2];
    const float* out_w  = (const float*)d_in[3];
    const float* out_b  = (const float*)d_in[4];
    const float* pre_g  = (const float*)d_in[5];
    const float* pre_b  = (const float*)d_in[6];
    const float* lcm_g  = (const float*)d_in[7];
    const float* lcm_b  = (const float*)d_in[8];
    const float* ci_w   = (const float*)d_in[9];
    const float* ci_b   = (const float*)d_in[10];
    const float* bn_g   = (const float*)d_in[11];
    const float* bn_b   = (const float*)d_in[12];
    const float* co_w   = (const float*)d_in[13];
    const float* co_b   = (const float*)d_in[14];
    float* out = (float*)d_out;

    float *p_normed, *p_qkv, *p_attn, *p_attnproj, *p_t, *p_wqkvT, *p_woutT;
    cudaGetSymbolAddress((void**)&p_normed,   g_normed);
    cudaGetSymbolAddress((void**)&p_qkv,      g_qkv);
    cudaGetSymbolAddress((void**)&p_attn,     g_attn);
    cudaGetSymbolAddress((void**)&p_attnproj, g_attnproj);
    cudaGetSymbolAddress((void**)&p_t,        g_t);
    cudaGetSymbolAddress((void**)&p_wqkvT,    g_wqkvT);
    cudaGetSymbolAddress((void**)&p_woutT,    g_woutT);

    // weight transposes ([K,N] -> [N,K])
    transpose_kernel<<<dim3(1536/32, 512/32), dim3(32,8)>>>(qkv_w, p_wqkvT, 512, 1536);
    transpose_kernel<<<dim3(512/32, 512/32), dim3(32,8)>>>(out_w, p_woutT, 512, 512);

    // 1. pre-layernorm
    ln_kernel<<<NTOK, 128>>>(x, pre_g, pre_b, p_normed);
    zero_kernel<<<(BB*HEADS*HD*HD + 255) / 256, 256>>>();
    // 2. qkv gemm (mma.sync tf32) + relu on q,k columns [0,1024)
    gemm_mma_kernel<<<dim3(1536/128, NTOK/128), 256>>>(
        p_normed, p_wqkvT, qkv_b, p_qkv, 1536, 1024);
    // 3. kv outer-product + ksum
    kv_kernel<<<dim3(BB*HEADS, 16), 256>>>(p_qkv);
    // 4. attention apply
    attn_kernel<<<dim3(BB*HEADS, 128), 256>>>(p_qkv, p_attn);
    // 5. output projection (mma.sync tf32)
    gemm_mma_kernel<<<dim3(CC/128, NTOK/128), 256>>>(
        p_attn, p_woutT, out_b, p_attnproj, 512, 0);
    // 6. lcm layernorm
    ln_kernel<<<NTOK, 128>>>(p_attnproj, lcm_g, lcm_b, p_t);
    // 7. conv1 + gelu + bn stats
    conv1_kernel<<<dim3(64, CC/32, BB), 256>>>(p_t, ci_w, ci_b);
    // 8. bn apply + conv2 + residual sum -> out
    conv2_kernel<<<dim3(64, CC/32, BB), 256>>>(x, co_w, co_b, bn_g, bn_b, out);
}

// round 8
// speedup vs baseline: 2.1928x; 1.2274x over previous
#include <cuda_runtime.h>
#include <cuda_bf16.h>
#include <math.h>
#include <cstdint>

#define BB    8
#define NN    4096
#define CC    512
#define NTOK  (BB*NN)        // 32768 tokens
#define HEADS 8
#define HD    64
#define HH    64
#define WW    64
#define EPSF  1e-5f
#define CLAMPF 100.0f

// ---------------- scratch (static device globals; no runtime alloc) ----------
__device__ __nv_bfloat16 g_normedh[NTOK*CC];       // 32 MB (GEMM1 A)
__device__ float g_qkv[(size_t)NTOK*3*CC];         // 192 MB
__device__ __nv_bfloat16 g_attnh[NTOK*CC];         // 32 MB (GEMM2 A)
__device__ float g_attnproj[NTOK*CC];              // 64 MB
__device__ float g_t[NTOK*CC];                     // 64 MB
__device__ float g_y[NTOK*CC];                     // 64 MB
__device__ float g_kv[BB*HEADS*HD*HD];
__device__ float g_ksum[BB*HEADS*HD];
__device__ float g_sum[CC];
__device__ float g_sumsq[CC];
__device__ __nv_bfloat16 g_wqkvTh[3*CC*CC];        // [1536,512] bf16 transposed
__device__ __nv_bfloat16 g_woutTh[CC*CC];          // [512,512]  bf16 transposed

// ============================ PTX helpers ====================================
__device__ __forceinline__ uint32_t smem_u32(const void* p){
    uint32_t a;
    asm("{ .reg .u64 t; cvta.to.shared.u64 t, %1; cvt.u32.u64 %0, t; }"
        : "=r"(a) : "l"(p));
    return a;
}
__device__ __forceinline__ void cpa16(uint32_t dst, const void* src){
    asm volatile("cp.async.ca.shared.global [%0], [%1], 16;"
                 :: "r"(dst), "l"(src) : "memory");
}
__device__ __forceinline__ void cpa_commit(){
    asm volatile("cp.async.commit_group;" ::: "memory");
}
template<int N> __device__ __forceinline__ void cpa_wait(){
    asm volatile("cp.async.wait_group %0;" :: "n"(N) : "memory");
}
__device__ __forceinline__ void mma_bf16(float* d, const uint32_t* a, const uint32_t* b){
    asm volatile("mma.sync.aligned.m16n8k16.row.col.f32.bf16.bf16.f32 "
        "{%0,%1,%2,%3}, {%4,%5,%6,%7}, {%8,%9}, {%0,%1,%2,%3};"
        : "+f"(d[0]), "+f"(d[1]), "+f"(d[2]), "+f"(d[3])
        : "r"(a[0]), "r"(a[1]), "r"(a[2]), "r"(a[3]), "r"(b[0]), "r"(b[1]));
}

// ============================ mma.sync bf16 GEMM =============================
// D[M,Nn] = A[M,512] @ Bt[Nn,512]^T + bias, relu on cols < nrelu.
// CTA tile 128x128, 8 warps (4m x 2n), warp tile 32x64. BK=32 bf16, dbl buffer.
#define GK    512
#define GBK   32
#define KPADH 40              // halves per row (80B stride; 20-bank permutation)
#define NKT   (GK/GBK)        // 16 k-tiles

__global__ void __launch_bounds__(256)
gemm_mma_kernel(const __nv_bfloat16* __restrict__ A,
                const __nv_bfloat16* __restrict__ Bt,
                const float* __restrict__ bias, float* __restrict__ Cout,
                int Nn, int nrelu)
{
    __shared__ __nv_bfloat16 As[2][128][KPADH];
    __shared__ __nv_bfloat16 Bs[2][128][KPADH];
    int tid = threadIdx.x;
    int wid = tid >> 5, lane = tid & 31;
    int gid = lane >> 2, tig = lane & 3;
    int warpM = (wid >> 1) * 32;
    int warpN = (wid & 1) * 64;
    int row0 = blockIdx.y * 128, col0 = blockIdx.x * 128;
    const __nv_bfloat16* Ab = A  + (size_t)row0 * GK;
    const __nv_bfloat16* Bb = Bt + (size_t)col0 * GK;

    // cp.async: 512 16B-chunks per operand per stage; 2 chunks each per thread
    int q0 = tid, q1 = tid + 256;
    int r0 = q0 >> 2, c0 = q0 & 3;       // row, 16B-chunk within 64B row
    int r1 = q1 >> 2, c1 = q1 & 3;
    uint32_t sA0 = smem_u32(&As[0][r0][0]) + c0 * 16;
    uint32_t sA1 = smem_u32(&As[0][r1][0]) + c1 * 16;
    uint32_t sB0 = smem_u32(&Bs[0][r0][0]) + c0 * 16;
    uint32_t sB1 = smem_u32(&Bs[0][r1][0]) + c1 * 16;
    const uint32_t stageOff = 128 * KPADH * 2;

    float acc[2][8][4];
    #pragma unroll
    for (int mi = 0; mi < 2; mi++)
        #pragma unroll
        for (int ni = 0; ni < 8; ni++)
            #pragma unroll
            for (int r = 0; r < 4; r++) acc[mi][ni][r] = 0.f;

    auto load_tile = [&](int t, int b){
        int k0 = t * GBK;
        uint32_t so = b * stageOff;
        cpa16(sA0 + so, Ab + (size_t)r0 * GK + k0 + c0 * 8);
        cpa16(sA1 + so, Ab + (size_t)r1 * GK + k0 + c1 * 8);
        cpa16(sB0 + so, Bb + (size_t)r0 * GK + k0 + c0 * 8);
        cpa16(sB1 + so, Bb + (size_t)r1 * GK + k0 + c1 * 8);
    };

    load_tile(0, 0);
    cpa_commit();

    for (int t = 0; t < NKT; t++){
        int cb = t & 1;
        if (t + 1 < NKT) load_tile(t + 1, (t + 1) & 1);
        cpa_commit();
        cpa_wait<1>();
        __syncthreads();
        #pragma unroll
        for (int ks = 0; ks < 2; ks++){
            int k0 = ks * 16;
            uint32_t a[2][4], b[8][2];
            #pragma unroll
            for (int mi = 0; mi < 2; mi++){
                int m = warpM + mi * 16 + gid;
                a[mi][0] = *(const uint32_t*)&As[cb][m    ][k0 + 2*tig];
                a[mi][1] = *(const uint32_t*)&As[cb][m + 8][k0 + 2*tig];
                a[mi][2] = *(const uint32_t*)&As[cb][m    ][k0 + 2*tig + 8];
                a[mi][3] = *(const uint32_t*)&As[cb][m + 8][k0 + 2*tig + 8];
            }
            #pragma unroll
            for (int ni = 0; ni < 8; ni++){
                int n = warpN + ni * 8 + gid;
                b[ni][0] = *(const uint32_t*)&Bs[cb][n][k0 + 2*tig];
                b[ni][1] = *(const uint32_t*)&Bs[cb][n][k0 + 2*tig + 8];
            }
            #pragma unroll
            for (int mi = 0; mi < 2; mi++)
                #pragma unroll
                for (int ni = 0; ni < 8; ni++)
                    mma_bf16(acc[mi][ni], a[mi], b[ni]);
        }
        __syncthreads();
    }

    // epilogue: bias + optional relu
    #pragma unroll
    for (int mi = 0; mi < 2; mi++){
        #pragma unroll
        for (int rr = 0; rr < 2; rr++){
            int r = row0 + warpM + mi * 16 + rr * 8 + gid;
            #pragma unroll
            for (int ni = 0; ni < 8; ni++){
                int c = col0 + warpN + ni * 8 + tig * 2;
                float2 o;
                o.x = acc[mi][ni][rr * 2 + 0] + bias[c + 0];
                o.y = acc[mi][ni][rr * 2 + 1] + bias[c + 1];
                if (c < nrelu){
                    o.x = fmaxf(o.x, 0.f);
                    o.y = fmaxf(o.y, 0.f);
                }
                *(float2*)(Cout + (size_t)r * Nn + c) = o;
            }
        }
    }
}

// ---------------- weight transpose -> bf16: out[n][k] = bf16(in[k][n]) -------
__global__ void transpose_kernel(const float* __restrict__ in,
                                 __nv_bfloat16* __restrict__ outp, int R, int Cc)
{
    __shared__ float tile[32][33];
    int bx = blockIdx.x * 32, by = blockIdx.y * 32;
    int tx = threadIdx.x, ty = threadIdx.y;   // 32 x 8
    #pragma unroll
    for (int i = 0; i < 32; i += 8)
        tile[ty + i][tx] = in[(size_t)(by + ty + i) * Cc + bx + tx];
    __syncthreads();
    #pragma unroll
    for (int i = 0; i < 32; i += 8)
        outp[(size_t)(bx + ty + i) * R + by + tx] = __float2bfloat16(tile[tx][ty + i]);
}

// ---------------- layernorm over C=512, templated output dtype ---------------
template<typename OUT>
__global__ void ln_kernel(const float* __restrict__ in,
                          const float* __restrict__ gamma,
                          const float* __restrict__ beta,
                          OUT* __restrict__ out)
{
    int token = blockIdx.x;
    const float4* row = (const float4*)(in + (size_t)token * CC);
    int tid = threadIdx.x;
    float4 v = row[tid];
    float s  = v.x + v.y + v.z + v.w;
    float sq = v.x*v.x + v.y*v.y + v.z*v.z + v.w*v.w;
    #pragma unroll
    for (int o = 16; o; o >>= 1) {
        s  += __shfl_xor_sync(0xffffffffu, s,  o);
        sq += __shfl_xor_sync(0xffffffffu, sq, o);
    }
    __shared__ float ss[4], ssq[4];
    if ((tid & 31) == 0) { ss[tid >> 5] = s; ssq[tid >> 5] = sq; }
    __syncthreads();
    float ts = ss[0] + ss[1] + ss[2] + ss[3];
    float tq = ssq[0] + ssq[1] + ssq[2] + ssq[3];
    float mean = ts * (1.0f / CC);
    float var  = tq * (1.0f / CC) - mean * mean;
    float inv  = rsqrtf(var + EPSF);
    float4 g4 = ((const float4*)gamma)[tid];
    float4 b4 = ((const float4*)beta)[tid];
    float4 o;
    o.x = (v.x - mean) * inv * g4.x + b4.x;
    o.y = (v.y - mean) * inv * g4.y + b4.y;
    o.z = (v.z - mean) * inv * g4.z + b4.z;
    o.w = (v.w - mean) * inv * g4.w + b4.w;
    if constexpr (sizeof(OUT) == 4) {
        ((float4*)(out + (size_t)token * CC))[tid] = o;
    } else {
        __nv_bfloat162 p0{__float2bfloat16(o.x), __float2bfloat16(o.y)};
        __nv_bfloat162 p1{__float2bfloat16(o.z), __float2bfloat16(o.w)};
        uint2 pk;
        pk.x = *(uint32_t*)&p0;
        pk.y = *(uint32_t*)&p1;
        ((uint2*)(out + (size_t)token * CC))[tid] = pk;
    }
}

// ---------------- zero scratch accumulators ---------------------------------
__global__ void zero_kernel()
{
    int i = blockIdx.x * blockDim.x + threadIdx.x;
    if (i < BB*HEADS*HD*HD) g_kv[i] = 0.f;
    if (i < BB*HEADS*HD)    g_ksum[i] = 0.f;
    if (i < CC)           { g_sum[i] = 0.f; g_sumsq[i] = 0.f; }
}

// ---------------- kv = k^T v per (b,h); ksum = sum_n k -----------------------
__global__ __launch_bounds__(256)
void kv_kernel(const float* __restrict__ qkv)
{
    int bh = blockIdx.x;
    int b = bh >> 3, h = bh & 7;
    const float* kbase = qkv + (size_t)(b*NN)*1536 +  512 + h*64;
    const float* vbase = qkv + (size_t)(b*NN)*1536 + 1024 + h*64;
    __shared__ float ks[64][64];
    __shared__ float vs[64][64];
    int tid = threadIdx.x;
    int lr = tid >> 4;
    int lc = (tid & 15) * 4;
    int ty = tid >> 4, tx = tid & 15;
    float acc[4][4];
    #pragma unroll
    for (int i = 0; i < 4; i++)
        #pragma unroll
        for (int j = 0; j < 4; j++) acc[i][j] = 0.f;
    float ksum4[4] = {0.f, 0.f, 0.f, 0.f};
    int n0 = blockIdx.y * 256;
    for (int s = 0; s < 4; s++) {
        int base = n0 + s * 64;
        #pragma unroll
        for (int p = 0; p < 4; p++) {
            int r = p * 16 + lr;
            float4 kk = *(const float4*)(kbase + (size_t)(base + r) * 1536 + lc);
            float4 vv = *(const float4*)(vbase + (size_t)(base + r) * 1536 + lc);
            *(float4*)&ks[r][lc] = kk;
            *(float4*)&vs[r][lc] = vv;
            ksum4[0] += kk.x; ksum4[1] += kk.y; ksum4[2] += kk.z; ksum4[3] += kk.w;
        }
        __syncthreads();
        #pragma unroll 8
        for (int n = 0; n < 64; n++) {
            float rk[4], rv[4];
            *(float4*)rk = *(const float4*)&ks[n][ty * 4];
            *(float4*)rv = *(const float4*)&vs[n][tx * 4];
            #pragma unroll
            for (int i = 0; i < 4; i++)
                #pragma unroll
                for (int j = 0; j < 4; j++)
                    acc[i][j] += rk[i] * rv[j];
        }
        __syncthreads();
    }
    float* kvout = g_kv + bh * 4096;
    #pragma unroll
    for (int i = 0; i < 4; i++)
        #pragma unroll
        for (int j = 0; j < 4; j++)
            atomicAdd(&kvout[(ty*4 + i) * 64 + tx*4 + j], acc[i][j]);
    #pragma unroll
    for (int i = 0; i < 4; i++)
        atomicAdd(&g_ksum[bh * 64 + lc + i], ksum4[i]);
}

// ---------------- attn = (q @ kv) / max(q . norm, 100) -> bf16 ---------------
__global__ __launch_bounds__(256)
void attn_kernel(const float* __restrict__ qkv, __nv_bfloat16* __restrict__ attn)
{
    int bh = blockIdx.x;
    int b = bh >> 3, h = bh & 7;
    __shared__ float kvs[64][64];
    __shared__ float norms[64];
    __shared__ float qs[4][64];
    int tid = threadIdx.x;
    for (int i = tid; i < 4096; i += 256)
        kvs[i >> 6][i & 63] = g_kv[bh * 4096 + i];
    if (tid < 64) norms[tid] = fmaxf(g_ksum[bh * 64 + tid], CLAMPF);
    __syncthreads();
    int tg = tid >> 6;
    int e  = tid & 63;
    const float* qbase = qkv + (size_t)(b*NN)*1536 + h*64;
    for (int it = 0; it < 8; it++) {
        int n = blockIdx.y * 32 + it * 4 + tg;
        qs[tg][e] = qbase[(size_t)n * 1536 + e];
        __syncthreads();
        float acc = 0.f, den = 0.f;
        #pragma unroll
        for (int d = 0; d < 64; d++) {
            float qd = qs[tg][d];
            acc += qd * kvs[d][e];
            den += qd * norms[d];
        }
        den = fmaxf(den, CLAMPF);
        attn[(size_t)(b*NN + n) * CC + h*64 + e] = __float2bfloat16(acc / den);
        __syncthreads();
    }
}

// ---------------- conv1: depthwise 7x7 + bias + gelu + channel stats ---------
__global__ __launch_bounds__(256)
void conv1_kernel(const float* __restrict__ t, const float* __restrict__ cw,
                  const float* __restrict__ cb)
{
    int b  = blockIdx.z;
    int c0 = blockIdx.y * 32;
    int h0 = (blockIdx.x >> 3) * 8;
    int w0 = (blockIdx.x & 7) * 8;
    __shared__ float ins[14][14][32];
    __shared__ float ws[32][49];
    __shared__ float rsum[8][32], rsq[8][32];
    int tid = threadIdx.x;
    for (int i = tid; i < 32 * 49; i += 256)
        ws[i / 49][i % 49] = cw[(c0 + i / 49) * 49 + (i % 49)];
    for (int i = tid; i < 14 * 14 * 32; i += 256) {
        int ic = i & 31; int pos = i >> 5;
        int iw = pos % 14, ih = pos / 14;
        int gh = h0 + ih - 3, gw = w0 + iw - 3;
        float v = 0.f;
        if (gh >= 0 && gh < HH && gw >= 0 && gw < WW)
            v = t[((size_t)(b*NN) + gh*WW + gw) * CC + c0 + ic];
        ins[ih][iw][ic] = v;
    }
    __syncthreads();
    int oc = tid & 31;
    int ow = tid >> 5;
    float bias = cb[c0 + oc];
    float psum = 0.f, psq = 0.f;
    for (int oh = 0; oh < 8; oh++) {
        float acc = bias;
        #pragma unroll
        for (int dh = 0; dh < 7; dh++)
            #pragma unroll
            for (int dw = 0; dw < 7; dw++)
                acc += ins[oh + dh][ow + dw][oc] * ws[oc][dh * 7 + dw];
        float yv = acc * normcdff(acc);
        g_y[((size_t)(b*NN) + (h0+oh)*WW + (w0+ow)) * CC + c0 + oc] = yv;
        psum += yv; psq += yv * yv;
    }
    rsum[ow][oc] = psum; rsq[ow][oc] = psq;
    __syncthreads();
    if (tid < 32) {
        float s = 0.f, q = 0.f;
        #pragma unroll
        for (int i = 0; i < 8; i++) { s += rsum[i][tid]; q += rsq[i][tid]; }
        atomicAdd(&g_sum[c0 + tid], s);
        atomicAdd(&g_sumsq[c0 + tid], q);
    }
}

// ---------------- conv2: BN-apply + depthwise 7x7 + triple residual ----------
__global__ __launch_bounds__(256)
void conv2_kernel(const float* __restrict__ x, const float* __restrict__ cw,
                  const float* __restrict__ cb, const float* __restrict__ bng,
                  const float* __restrict__ bnb, float* __restrict__ out)
{
    int b  = blockIdx.z;
    int c0 = blockIdx.y * 32;
    int h0 = (blockIdx.x >> 3) * 8;
    int w0 = (blockIdx.x & 7) * 8;
    __shared__ float ins[14][14][32];
    __shared__ float ws[32][49];
    __shared__ float scs[32], shs[32];
    int tid = threadIdx.x;
    if (tid < 32) {
        int c = c0 + tid;
        float m   = g_sum[c]   * (1.0f / (float)NTOK);
        float var = g_sumsq[c] * (1.0f / (float)NTOK) - m * m;
        float inv = rsqrtf(var + EPSF);
        float sc = bng[c] * inv;
        scs[tid] = sc;
        shs[tid] = bnb[c] - m * sc;
    }
    __syncthreads();
    for (int i = tid; i < 32 * 49; i += 256)
        ws[i / 49][i % 49] = cw[(c0 + i / 49) * 49 + (i % 49)];
    for (int i = tid; i < 14 * 14 * 32; i += 256) {
        int ic = i & 31; int pos = i >> 5;
        int iw = pos % 14, ih = pos / 14;
        int gh = h0 + ih - 3, gw = w0 + iw - 3;
        float v = 0.f;
        if (gh >= 0 && gh < HH && gw >= 0 && gw < WW)
            v = g_y[((size_t)(b*NN) + gh*WW + gw) * CC + c0 + ic] * scs[ic] + shs[ic];
        ins[ih][iw][ic] = v;
    }
    __syncthreads();
    int oc = tid & 31;
    int ow = tid >> 5;
    float bias = cb[c0 + oc];
    for (int oh = 0; oh < 8; oh++) {
        float acc = bias;
        #pragma unroll
        for (int dh = 0; dh < 7; dh++)
            #pragma unroll
            for (int dw = 0; dw < 7; dw++)
                acc += ins[oh + dh][ow + dw][oc] * ws[oc][dh * 7 + dw];
        size_t idx = ((size_t)(b*NN) + (h0+oh)*WW + (w0+ow)) * CC + c0 + oc;
        out[idx] = x[idx] + g_attnproj[idx] + acc;
    }
}

// ---------------- launch ----------------------------------------------------
extern "C" void kernel_launch(void* const* d_in, const int* in_sizes, int n_in,
                              void* d_out, int out_size)
{
    const float* x      = (const float*)d_in[0];
    const float* qkv_w  = (const float*)d_in[1];
    const float* qkv_b  = (const float*)d_in[2];
    const float* out_w  = (const float*)d_in[3];
    const float* out_b  = (const float*)d_in[4];
    const float* pre_g  = (const float*)d_in[5];
    const float* pre_b  = (const float*)d_in[6];
    const float* lcm_g  = (const float*)d_in[7];
    const float* lcm_b  = (const float*)d_in[8];
    const float* ci_w   = (const float*)d_in[9];
    const float* ci_b   = (const float*)d_in[10];
    const float* bn_g   = (const float*)d_in[11];
    const float* bn_b   = (const float*)d_in[12];
    const float* co_w   = (const float*)d_in[13];
    const float* co_b   = (const float*)d_in[14];
    float* out = (float*)d_out;

    __nv_bfloat16 *p_normedh, *p_attnh, *p_wqkvTh, *p_woutTh;
    float *p_qkv, *p_attnproj, *p_t;
    cudaGetSymbolAddress((void**)&p_normedh,  g_normedh);
    cudaGetSymbolAddress((void**)&p_qkv,      g_qkv);
    cudaGetSymbolAddress((void**)&p_attnh,    g_attnh);
    cudaGetSymbolAddress((void**)&p_attnproj, g_attnproj);
    cudaGetSymbolAddress((void**)&p_t,        g_t);
    cudaGetSymbolAddress((void**)&p_wqkvTh,   g_wqkvTh);
    cudaGetSymbolAddress((void**)&p_woutTh,   g_woutTh);

    // weight transposes ([K,N] -> [N,K], bf16)
    transpose_kernel<<<dim3(1536/32, 512/32), dim3(32,8)>>>(qkv_w, p_wqkvTh, 512, 1536);
    transpose_kernel<<<dim3(512/32, 512/32), dim3(32,8)>>>(out_w, p_woutTh, 512, 512);

    // 1. pre-layernorm -> bf16
    ln_kernel<__nv_bfloat16><<<NTOK, 128>>>(x, pre_g, pre_b, p_normedh);
    zero_kernel<<<(BB*HEADS*HD*HD + 255) / 256, 256>>>();
    // 2. qkv gemm (mma.sync bf16) + relu on q,k columns [0,1024)
    gemm_mma_kernel<<<dim3(1536/128, NTOK/128), 256>>>(
        p_normedh, p_wqkvTh, qkv_b, p_qkv, 1536, 1024);
    // 3. kv outer-product + ksum
    kv_kernel<<<dim3(BB*HEADS, 16), 256>>>(p_qkv);
    // 4. attention apply -> bf16
    attn_kernel<<<dim3(BB*HEADS, 128), 256>>>(p_qkv, p_attnh);
    // 5. output projection (mma.sync bf16)
    gemm_mma_kernel<<<dim3(CC/128, NTOK/128), 256>>>(
        p_attnh, p_woutTh, out_b, p_attnproj, 512, 0);
    // 6. lcm layernorm -> f32
    ln_kernel<float><<<NTOK, 128>>>(p_attnproj, lcm_g, lcm_b, p_t);
    // 7. conv1 + gelu + bn stats
    conv1_kernel<<<dim3(64, CC/32, BB), 256>>>(p_t, ci_w, ci_b);
    // 8. bn apply + conv2 + residual sum -> out
    conv2_kernel<<<dim3(64, CC/32, BB), 256>>>(x, co_w, co_b, bn_g, bn_b, out);
}

// round 9
// speedup vs baseline: 2.3696x; 1.0806x over previous
#include <cuda_runtime.h>
#include <cuda_fp16.h>
#include <math.h>
#include <cstdint>

#define BB    8
#define NN    4096
#define CC    512
#define NTOK  (BB*NN)        // 32768 tokens
#define HEADS 8
#define HD    64
#define HH    64
#define WW    64
#define EPSF  1e-5f
#define CLAMPF 100.0f

// ---------------- scratch (static device globals; no runtime alloc) ----------
__device__ __half g_normedh[NTOK*CC];              // 32 MB (GEMM1 A)
__device__ __half g_qkvh[(size_t)NTOK*3*CC];       // 96 MB (GEMM1 out, fp16)
__device__ __half g_attnh[NTOK*CC];                // 32 MB (GEMM2 A)
__device__ float g_attnproj[NTOK*CC];              // 64 MB
__device__ float g_t[NTOK*CC];                     // 64 MB
__device__ float g_y[NTOK*CC];                     // 64 MB
__device__ float g_kv[BB*HEADS*HD*HD];
__device__ float g_ksum[BB*HEADS*HD];
__device__ float g_sum[CC];
__device__ float g_sumsq[CC];
__device__ __half g_wqkvTh[3*CC*CC];               // [1536,512] fp16 transposed
__device__ __half g_woutTh[CC*CC];                 // [512,512]  fp16 transposed

// ============================ PTX helpers ====================================
__device__ __forceinline__ uint32_t smem_u32(const void* p){
    uint32_t a;
    asm("{ .reg .u64 t; cvta.to.shared.u64 t, %1; cvt.u32.u64 %0, t; }"
        : "=r"(a) : "l"(p));
    return a;
}
__device__ __forceinline__ void cpa16(uint32_t dst, const void* src){
    asm volatile("cp.async.ca.shared.global [%0], [%1], 16;"
                 :: "r"(dst), "l"(src) : "memory");
}
__device__ __forceinline__ void cpa_commit(){
    asm volatile("cp.async.commit_group;" ::: "memory");
}
template<int N> __device__ __forceinline__ void cpa_wait(){
    asm volatile("cp.async.wait_group %0;" :: "n"(N) : "memory");
}
__device__ __forceinline__ void mma_f16(float* d, const uint32_t* a, const uint32_t* b){
    asm volatile("mma.sync.aligned.m16n8k16.row.col.f32.f16.f16.f32 "
        "{%0,%1,%2,%3}, {%4,%5,%6,%7}, {%8,%9}, {%0,%1,%2,%3};"
        : "+f"(d[0]), "+f"(d[1]), "+f"(d[2]), "+f"(d[3])
        : "r"(a[0]), "r"(a[1]), "r"(a[2]), "r"(a[3]), "r"(b[0]), "r"(b[1]));
}

// ============================ mma.sync fp16 GEMM =============================
// D[M,Nn] = A[M,512] @ Bt[Nn,512]^T + bias, relu on cols < nrelu.
// CTA tile 128x128, 8 warps (4m x 2n), warp tile 32x64. BK=32 fp16, dbl buffer.
#define GK    512
#define GBK   32
#define KPADH 40              // halves per row (80B stride; odd-bank permutation)
#define NKT   (GK/GBK)        // 16 k-tiles

template<typename OUT>
__global__ void __launch_bounds__(256)
gemm_mma_kernel(const __half* __restrict__ A,
                const __half* __restrict__ Bt,
                const float* __restrict__ bias, OUT* __restrict__ Cout,
                int Nn, int nrelu)
{
    __shared__ __half As[2][128][KPADH];
    __shared__ __half Bs[2][128][KPADH];
    int tid = threadIdx.x;
    int wid = tid >> 5, lane = tid & 31;
    int gid = lane >> 2, tig = lane & 3;
    int warpM = (wid >> 1) * 32;
    int warpN = (wid & 1) * 64;
    int row0 = blockIdx.y * 128, col0 = blockIdx.x * 128;
    const __half* Ab = A  + (size_t)row0 * GK;
    const __half* Bb = Bt + (size_t)col0 * GK;

    int q0 = tid, q1 = tid + 256;
    int r0 = q0 >> 2, c0 = q0 & 3;
    int r1 = q1 >> 2, c1 = q1 & 3;
    uint32_t sA0 = smem_u32(&As[0][r0][0]) + c0 * 16;
    uint32_t sA1 = smem_u32(&As[0][r1][0]) + c1 * 16;
    uint32_t sB0 = smem_u32(&Bs[0][r0][0]) + c0 * 16;
    uint32_t sB1 = smem_u32(&Bs[0][r1][0]) + c1 * 16;
    const uint32_t stageOff = 128 * KPADH * 2;

    float acc[2][8][4];
    #pragma unroll
    for (int mi = 0; mi < 2; mi++)
        #pragma unroll
        for (int ni = 0; ni < 8; ni++)
            #pragma unroll
            for (int r = 0; r < 4; r++) acc[mi][ni][r] = 0.f;

    auto load_tile = [&](int t, int b){
        int k0 = t * GBK;
        uint32_t so = b * stageOff;
        cpa16(sA0 + so, Ab + (size_t)r0 * GK + k0 + c0 * 8);
        cpa16(sA1 + so, Ab + (size_t)r1 * GK + k0 + c1 * 8);
        cpa16(sB0 + so, Bb + (size_t)r0 * GK + k0 + c0 * 8);
        cpa16(sB1 + so, Bb + (size_t)r1 * GK + k0 + c1 * 8);
    };

    load_tile(0, 0);
    cpa_commit();

    for (int t = 0; t < NKT; t++){
        int cb = t & 1;
        if (t + 1 < NKT) load_tile(t + 1, (t + 1) & 1);
        cpa_commit();
        cpa_wait<1>();
        __syncthreads();
        #pragma unroll
        for (int ks = 0; ks < 2; ks++){
            int k0 = ks * 16;
            uint32_t a[2][4], b[8][2];
            #pragma unroll
            for (int mi = 0; mi < 2; mi++){
                int m = warpM + mi * 16 + gid;
                a[mi][0] = *(const uint32_t*)&As[cb][m    ][k0 + 2*tig];
                a[mi][1] = *(const uint32_t*)&As[cb][m + 8][k0 + 2*tig];
                a[mi][2] = *(const uint32_t*)&As[cb][m    ][k0 + 2*tig + 8];
                a[mi][3] = *(const uint32_t*)&As[cb][m + 8][k0 + 2*tig + 8];
            }
            #pragma unroll
            for (int ni = 0; ni < 8; ni++){
                int n = warpN + ni * 8 + gid;
                b[ni][0] = *(const uint32_t*)&Bs[cb][n][k0 + 2*tig];
                b[ni][1] = *(const uint32_t*)&Bs[cb][n][k0 + 2*tig + 8];
            }
            #pragma unroll
            for (int mi = 0; mi < 2; mi++)
                #pragma unroll
                for (int ni = 0; ni < 8; ni++)
                    mma_f16(acc[mi][ni], a[mi], b[ni]);
        }
        __syncthreads();
    }

    // epilogue: bias + optional relu
    #pragma unroll
    for (int mi = 0; mi < 2; mi++){
        #pragma unroll
        for (int rr = 0; rr < 2; rr++){
            int r = row0 + warpM + mi * 16 + rr * 8 + gid;
            #pragma unroll
            for (int ni = 0; ni < 8; ni++){
                int c = col0 + warpN + ni * 8 + tig * 2;
                float ox = acc[mi][ni][rr * 2 + 0] + bias[c + 0];
                float oy = acc[mi][ni][rr * 2 + 1] + bias[c + 1];
                if (c < nrelu){
                    ox = fmaxf(ox, 0.f);
                    oy = fmaxf(oy, 0.f);
                }
                if constexpr (sizeof(OUT) == 4) {
                    float2 o{ox, oy};
                    *(float2*)((float*)Cout + (size_t)r * Nn + c) = o;
                } else {
                    __half2 o{__float2half(ox), __float2half(oy)};
                    *(__half2*)((__half*)Cout + (size_t)r * Nn + c) = o;
                }
            }
        }
    }
}

// ---------------- weight transpose -> fp16: out[n][k] = h(in[k][n]) ----------
__global__ void transpose_kernel(const float* __restrict__ in,
                                 __half* __restrict__ outp, int R, int Cc)
{
    __shared__ float tile[32][33];
    int bx = blockIdx.x * 32, by = blockIdx.y * 32;
    int tx = threadIdx.x, ty = threadIdx.y;   // 32 x 8
    #pragma unroll
    for (int i = 0; i < 32; i += 8)
        tile[ty + i][tx] = in[(size_t)(by + ty + i) * Cc + bx + tx];
    __syncthreads();
    #pragma unroll
    for (int i = 0; i < 32; i += 8)
        outp[(size_t)(bx + ty + i) * R + by + tx] = __float2half(tile[tx][ty + i]);
}

// ---------------- layernorm over C=512, templated output dtype ---------------
template<typename OUT>
__global__ void ln_kernel(const float* __restrict__ in,
                          const float* __restrict__ gamma,
                          const float* __restrict__ beta,
                          OUT* __restrict__ out)
{
    int token = blockIdx.x;
    const float4* row = (const float4*)(in + (size_t)token * CC);
    int tid = threadIdx.x;
    float4 v = row[tid];
    float s  = v.x + v.y + v.z + v.w;
    float sq = v.x*v.x + v.y*v.y + v.z*v.z + v.w*v.w;
    #pragma unroll
    for (int o = 16; o; o >>= 1) {
        s  += __shfl_xor_sync(0xffffffffu, s,  o);
        sq += __shfl_xor_sync(0xffffffffu, sq, o);
    }
    __shared__ float ss[4], ssq[4];
    if ((tid & 31) == 0) { ss[tid >> 5] = s; ssq[tid >> 5] = sq; }
    __syncthreads();
    float ts = ss[0] + ss[1] + ss[2] + ss[3];
    float tq = ssq[0] + ssq[1] + ssq[2] + ssq[3];
    float mean = ts * (1.0f / CC);
    float var  = tq * (1.0f / CC) - mean * mean;
    float inv  = rsqrtf(var + EPSF);
    float4 g4 = ((const float4*)gamma)[tid];
    float4 b4 = ((const float4*)beta)[tid];
    float4 o;
    o.x = (v.x - mean) * inv * g4.x + b4.x;
    o.y = (v.y - mean) * inv * g4.y + b4.y;
    o.z = (v.z - mean) * inv * g4.z + b4.z;
    o.w = (v.w - mean) * inv * g4.w + b4.w;
    if constexpr (sizeof(OUT) == 4) {
        ((float4*)(out + (size_t)token * CC))[tid] = o;
    } else {
        __half2 p0{__float2half(o.x), __float2half(o.y)};
        __half2 p1{__float2half(o.z), __float2half(o.w)};
        uint2 pk;
        pk.x = *(uint32_t*)&p0;
        pk.y = *(uint32_t*)&p1;
        ((uint2*)(out + (size_t)token * CC))[tid] = pk;
    }
}

// ---------------- zero scratch accumulators ---------------------------------
__global__ void zero_kernel()
{
    int i = blockIdx.x * blockDim.x + threadIdx.x;
    if (i < BB*HEADS*HD*HD) g_kv[i] = 0.f;
    if (i < BB*HEADS*HD)    g_ksum[i] = 0.f;
    if (i < CC)           { g_sum[i] = 0.f; g_sumsq[i] = 0.f; }
}

// ---------------- kv = k^T v per (b,h); ksum = sum_n k (fp16 in) -------------
__global__ __launch_bounds__(256)
void kv_kernel(const __half* __restrict__ qkv)
{
    int bh = blockIdx.x;
    int b = bh >> 3, h = bh & 7;
    const __half* kbase = qkv + (size_t)(b*NN)*1536 +  512 + h*64;
    const __half* vbase = qkv + (size_t)(b*NN)*1536 + 1024 + h*64;
    __shared__ float ks[64][64];
    __shared__ float vs[64][64];
    int tid = threadIdx.x;
    int lr  = tid >> 3;           // 0..31 (row within 32-row half-pass)
    int lc8 = (tid & 7) * 8;      // 0..56 (8 halves per thread)
    int ty = tid >> 4, tx = tid & 15;
    float acc[4][4];
    #pragma unroll
    for (int i = 0; i < 4; i++)
        #pragma unroll
        for (int j = 0; j < 4; j++) acc[i][j] = 0.f;
    float ksum8[8];
    #pragma unroll
    for (int j = 0; j < 8; j++) ksum8[j] = 0.f;
    int n0 = blockIdx.y * 256;
    for (int s = 0; s < 4; s++) {
        int base = n0 + s * 64;
        #pragma unroll
        for (int p = 0; p < 2; p++) {
            int r = p * 32 + lr;
            uint4 kk = *(const uint4*)(kbase + (size_t)(base + r) * 1536 + lc8);
            uint4 vv = *(const uint4*)(vbase + (size_t)(base + r) * 1536 + lc8);
            const __half2* kh = (const __half2*)&kk;
            const __half2* vh = (const __half2*)&vv;
            #pragma unroll
            for (int j = 0; j < 4; j++){
                float2 kf = __half22float2(kh[j]);
                float2 vf = __half22float2(vh[j]);
                ks[r][lc8 + 2*j    ] = kf.x;
                ks[r][lc8 + 2*j + 1] = kf.y;
                vs[r][lc8 + 2*j    ] = vf.x;
                vs[r][lc8 + 2*j + 1] = vf.y;
                ksum8[2*j]     += kf.x;
                ksum8[2*j + 1] += kf.y;
            }
        }
        __syncthreads();
        #pragma unroll 8
        for (int n = 0; n < 64; n++) {
            float rk[4], rv[4];
            *(float4*)rk = *(const float4*)&ks[n][ty * 4];
            *(float4*)rv = *(const float4*)&vs[n][tx * 4];
            #pragma unroll
            for (int i = 0; i < 4; i++)
                #pragma unroll
                for (int j = 0; j < 4; j++)
                    acc[i][j] += rk[i] * rv[j];
        }
        __syncthreads();
    }
    float* kvout = g_kv + bh * 4096;
    #pragma unroll
    for (int i = 0; i < 4; i++)
        #pragma unroll
        for (int j = 0; j < 4; j++)
            atomicAdd(&kvout[(ty*4 + i) * 64 + tx*4 + j], acc[i][j]);
    // reduce ksum across the 4 lanes per warp sharing the same columns
    #pragma unroll
    for (int j = 0; j < 8; j++){
        ksum8[j] += __shfl_xor_sync(0xffffffffu, ksum8[j], 8);
        ksum8[j] += __shfl_xor_sync(0xffffffffu, ksum8[j], 16);
    }
    if ((tid & 31) < 8){
        #pragma unroll
        for (int j = 0; j < 8; j++)
            atomicAdd(&g_ksum[bh * 64 + lc8 + j], ksum8[j]);
    }
}

// ---------------- attn = (q @ kv) / max(q . norm, 100) -> fp16 ---------------
__global__ __launch_bounds__(256)
void attn_kernel(const __half* __restrict__ qkv, __half* __restrict__ attn)
{
    int bh = blockIdx.x;
    int b = bh >> 3, h = bh & 7;
    __shared__ float kvs[64][64];
    __shared__ float norms[64];
    __shared__ float qs[4][64];
    int tid = threadIdx.x;
    for (int i = tid; i < 4096; i += 256)
        kvs[i >> 6][i & 63] = g_kv[bh * 4096 + i];
    if (tid < 64) norms[tid] = fmaxf(g_ksum[bh * 64 + tid], CLAMPF);
    __syncthreads();
    int tg = tid >> 6;
    int e  = tid & 63;
    const __half* qbase = qkv + (size_t)(b*NN)*1536 + h*64;
    for (int it = 0; it < 8; it++) {
        int n = blockIdx.y * 32 + it * 4 + tg;
        qs[tg][e] = __half2float(qbase[(size_t)n * 1536 + e]);
        __syncthreads();
        float acc = 0.f, den = 0.f;
        #pragma unroll
        for (int d = 0; d < 64; d++) {
            float qd = qs[tg][d];
            acc += qd * kvs[d][e];
            den += qd * norms[d];
        }
        den = fmaxf(den, CLAMPF);
        attn[(size_t)(b*NN + n) * CC + h*64 + e] = __float2half(acc / den);
        __syncthreads();
    }
}

// ---------------- conv1: depthwise 7x7 + bias + gelu + channel stats ---------
// row-sliding: 98 input LDS per thread (vs 392), weights register-resident.
__global__ __launch_bounds__(256)
void conv1_kernel(const float* __restrict__ t, const float* __restrict__ cw,
                  const float* __restrict__ cb)
{
    int b  = blockIdx.z;
    int c0 = blockIdx.y * 32;
    int h0 = (blockIdx.x >> 3) * 8;
    int w0 = (blockIdx.x & 7) * 8;
    __shared__ float ins[14][14][32];
    __shared__ float ws[32][49];
    __shared__ float rsum[8][32], rsq[8][32];
    int tid = threadIdx.x;
    for (int i = tid; i < 32 * 49; i += 256)
        ws[i / 49][i % 49] = cw[(c0 + i / 49) * 49 + (i % 49)];
    for (int i = tid; i < 14 * 14 * 32; i += 256) {
        int ic = i & 31; int pos = i >> 5;
        int iw = pos % 14, ih = pos / 14;
        int gh = h0 + ih - 3, gw = w0 + iw - 3;
        float v = 0.f;
        if (gh >= 0 && gh < HH && gw >= 0 && gw < WW)
            v = t[((size_t)(b*NN) + gh*WW + gw) * CC + c0 + ic];
        ins[ih][iw][ic] = v;
    }
    __syncthreads();
    int oc = tid & 31;
    int ow = tid >> 5;
    float wr[49];
    #pragma unroll
    for (int j = 0; j < 49; j++) wr[j] = ws[oc][j];
    float bias = cb[c0 + oc];
    float acc[8];
    #pragma unroll
    for (int oh = 0; oh < 8; oh++) acc[oh] = bias;
    #pragma unroll
    for (int ih = 0; ih < 14; ih++){
        float v[7];
        #pragma unroll
        for (int dw = 0; dw < 7; dw++) v[dw] = ins[ih][ow + dw][oc];
        #pragma unroll
        for (int oh = 0; oh < 8; oh++){
            int dh = ih - oh;
            if (dh >= 0 && dh < 7){
                #pragma unroll
                for (int dw = 0; dw < 7; dw++)
                    acc[oh] += v[dw] * wr[dh * 7 + dw];
            }
        }
    }
    float psum = 0.f, psq = 0.f;
    #pragma unroll
    for (int oh = 0; oh < 8; oh++){
        float yv = acc[oh] * normcdff(acc[oh]);
        g_y[((size_t)(b*NN) + (h0+oh)*WW + (w0+ow)) * CC + c0 + oc] = yv;
        psum += yv; psq += yv * yv;
    }
    rsum[ow][oc] = psum; rsq[ow][oc] = psq;
    __syncthreads();
    if (tid < 32) {
        float s = 0.f, q = 0.f;
        #pragma unroll
        for (int i = 0; i < 8; i++) { s += rsum[i][tid]; q += rsq[i][tid]; }
        atomicAdd(&g_sum[c0 + tid], s);
        atomicAdd(&g_sumsq[c0 + tid], q);
    }
}

// ---------------- conv2: BN-apply + depthwise 7x7 + triple residual ----------
__global__ __launch_bounds__(256)
void conv2_kernel(const float* __restrict__ x, const float* __restrict__ cw,
                  const float* __restrict__ cb, const float* __restrict__ bng,
                  const float* __restrict__ bnb, float* __restrict__ out)
{
    int b  = blockIdx.z;
    int c0 = blockIdx.y * 32;
    int h0 = (blockIdx.x >> 3) * 8;
    int w0 = (blockIdx.x & 7) * 8;
    __shared__ float ins[14][14][32];
    __shared__ float ws[32][49];
    __shared__ float scs[32], shs[32];
    int tid = threadIdx.x;
    if (tid < 32) {
        int c = c0 + tid;
        float m   = g_sum[c]   * (1.0f / (float)NTOK);
        float var = g_sumsq[c] * (1.0f / (float)NTOK) - m * m;
        float inv = rsqrtf(var + EPSF);
        float sc = bng[c] * inv;
        scs[tid] = sc;
        shs[tid] = bnb[c] - m * sc;
    }
    __syncthreads();
    for (int i = tid; i < 32 * 49; i += 256)
        ws[i / 49][i % 49] = cw[(c0 + i / 49) * 49 + (i % 49)];
    for (int i = tid; i < 14 * 14 * 32; i += 256) {
        int ic = i & 31; int pos = i >> 5;
        int iw = pos % 14, ih = pos / 14;
        int gh = h0 + ih - 3, gw = w0 + iw - 3;
        float v = 0.f;
        if (gh >= 0 && gh < HH && gw >= 0 && gw < WW)
            v = g_y[((size_t)(b*NN) + gh*WW + gw) * CC + c0 + ic] * scs[ic] + shs[ic];
        ins[ih][iw][ic] = v;
    }
    __syncthreads();
    int oc = tid & 31;
    int ow = tid >> 5;
    float wr[49];
    #pragma unroll
    for (int j = 0; j < 49; j++) wr[j] = ws[oc][j];
    float bias = cb[c0 + oc];
    float acc[8];
    #pragma unroll
    for (int oh = 0; oh < 8; oh++) acc[oh] = bias;
    #pragma unroll
    for (int ih = 0; ih < 14; ih++){
        float v[7];
        #pragma unroll
        for (int dw = 0; dw < 7; dw++) v[dw] = ins[ih][ow + dw][oc];
        #pragma unroll
        for (int oh = 0; oh < 8; oh++){
            int dh = ih - oh;
            if (dh >= 0 && dh < 7){
                #pragma unroll
                for (int dw = 0; dw < 7; dw++)
                    acc[oh] += v[dw] * wr[dh * 7 + dw];
            }
        }
    }
    #pragma unroll
    for (int oh = 0; oh < 8; oh++){
        size_t idx = ((size_t)(b*NN) + (h0+oh)*WW + (w0+ow)) * CC + c0 + oc;
        out[idx] = x[idx] + g_attnproj[idx] + acc[oh];
    }
}

// ---------------- launch ----------------------------------------------------
extern "C" void kernel_launch(void* const* d_in, const int* in_sizes, int n_in,
                              void* d_out, int out_size)
{
    const float* x      = (const float*)d_in[0];
    const float* qkv_w  = (const float*)d_in[1];
    const float* qkv_b  = (const float*)d_in[2];
    const float* out_w  = (const float*)d_in[3];
    const float* out_b  = (const float*)d_in[4];
    const float* pre_g  = (const float*)d_in[5];
    const float* pre_b  = (const float*)d_in[6];
    const float* lcm_g  = (const float*)d_in[7];
    const float* lcm_b  = (const float*)d_in[8];
    const float* ci_w   = (const float*)d_in[9];
    const float* ci_b   = (const float*)d_in[10];
    const float* bn_g   = (const float*)d_in[11];
    const float* bn_b   = (const float*)d_in[12];
    const float* co_w   = (const float*)d_in[13];
    const float* co_b   = (const float*)d_in[14];
    float* out = (float*)d_out;

    __half *p_normedh, *p_qkvh, *p_attnh, *p_wqkvTh, *p_woutTh;
    float *p_attnproj, *p_t;
    cudaGetSymbolAddress((void**)&p_normedh,  g_normedh);
    cudaGetSymbolAddress((void**)&p_qkvh,     g_qkvh);
    cudaGetSymbolAddress((void**)&p_attnh,    g_attnh);
    cudaGetSymbolAddress((void**)&p_attnproj, g_attnproj);
    cudaGetSymbolAddress((void**)&p_t,        g_t);
    cudaGetSymbolAddress((void**)&p_wqkvTh,   g_wqkvTh);
    cudaGetSymbolAddress((void**)&p_woutTh,   g_woutTh);

    // weight transposes ([K,N] -> [N,K], fp16)
    transpose_kernel<<<dim3(1536/32, 512/32), dim3(32,8)>>>(qkv_w, p_wqkvTh, 512, 1536);
    transpose_kernel<<<dim3(512/32, 512/32), dim3(32,8)>>>(out_w, p_woutTh, 512, 512);

    // 1. pre-layernorm -> fp16
    ln_kernel<__half><<<NTOK, 128>>>(x, pre_g, pre_b, p_normedh);
    zero_kernel<<<(BB*HEADS*HD*HD + 255) / 256, 256>>>();
    // 2. qkv gemm (mma.sync fp16) + relu on q,k columns [0,1024); out fp16
    gemm_mma_kernel<__half><<<dim3(1536/128, NTOK/128), 256>>>(
        p_normedh, p_wqkvTh, qkv_b, p_qkvh, 1536, 1024);
    // 3. kv outer-product + ksum (fp16 in, f32 accum)
    kv_kernel<<<dim3(BB*HEADS, 16), 256>>>(p_qkvh);
    // 4. attention apply -> fp16
    attn_kernel<<<dim3(BB*HEADS, 128), 256>>>(p_qkvh, p_attnh);
    // 5. output projection (mma.sync fp16) -> f32
    gemm_mma_kernel<float><<<dim3(CC/128, NTOK/128), 256>>>(
        p_attnh, p_woutTh, out_b, p_attnproj, 512, 0);
    // 6. lcm layernorm -> f32
    ln_kernel<float><<<NTOK, 128>>>(p_attnproj, lcm_g, lcm_b, p_t);
    // 7. conv1 + gelu + bn stats
    conv1_kernel<<<dim3(64, CC/32, BB), 256>>>(p_t, ci_w, ci_b);
    // 8. bn apply + conv2 + residual sum -> out
    conv2_kernel<<<dim3(64, CC/32, BB), 256>>>(x, co_w, co_b, bn_g, bn_b, out);
}